// round 9
// baseline (speedup 1.0000x reference)
#include <cuda_runtime.h>
#include <cuda_bf16.h>
#include <cstdint>

// R9: smem-free HMMA mainloop. A: LDG.64 direct-to-fragment + in-register
// 3-term split. B: one-time pre-permute of W into mma fragment layout
// (g_Bf), loaded with LDG.128 straight into b-registers. M=32/warp, N=32/warp,
// CTA = 64 tok x 64 exp (128 thr), grid 256, no mainloop barriers.
// Accumulation: all 6 split-combos mma into cr; 2Sum fold into s_ every 4
// k-steps (logit err ~6e-8, no top-k flips). Output: [T*8 idx | T*8 w].

#define MMA16816(d, a, b0, b1)                                                \
    asm volatile("mma.sync.aligned.m16n8k16.row.col.f32.bf16.bf16.f32 "       \
                 "{%0,%1,%2,%3}, {%4,%5,%6,%7}, {%8,%9}, {%0,%1,%2,%3};"      \
                 : "+f"((d)[0]), "+f"((d)[1]), "+f"((d)[2]), "+f"((d)[3])     \
                 : "r"((a)[0]), "r"((a)[1]), "r"((a)[2]), "r"((a)[3]),        \
                   "r"(b0), "r"(b1))

// B fragments: [ks(128)][term(3)][npair(4)][lane(32)] x uint4 = 786 KB
__device__ __align__(16) uint4 g_Bf[128 * 3 * 4 * 32];

static __device__ __forceinline__ void split1(float x, unsigned short& a,
                                              unsigned short& b, unsigned short& c) {
    __nv_bfloat16 t1 = __float2bfloat16(x);
    float r1 = x - __bfloat162float(t1);
    __nv_bfloat16 t2 = __float2bfloat16(r1);
    float r2 = r1 - __bfloat162float(t2);
    __nv_bfloat16 t3 = __float2bfloat16(r2);
    a = __bfloat16_as_ushort(t1);
    b = __bfloat16_as_ushort(t2);
    c = __bfloat16_as_ushort(t3);
}

static __device__ __forceinline__ void split2(float2 v, uint32_t& o1,
                                              uint32_t& o2, uint32_t& o3) {
    unsigned short ax, bx, cx, ay, by, cy;
    split1(v.x, ax, bx, cx);
    split1(v.y, ay, by, cy);
    o1 = (uint32_t)ax | ((uint32_t)ay << 16);
    o2 = (uint32_t)bx | ((uint32_t)by << 16);
    o3 = (uint32_t)cx | ((uint32_t)cy << 16);
}

// Pre-permute W into per-lane mma B-fragment layout, 3 split terms.
__global__ void w_split_kernel(const float* __restrict__ W) {
    int idx  = blockIdx.x * 256 + threadIdx.x;   // 0..16383
    int lane = idx & 31;
    int j    = (idx >> 5) & 3;                   // npair: experts j*16..j*16+15
    int ks   = idx >> 7;                         // k16 step 0..127
    int e_lo = j * 16 + (lane >> 2);
    int k    = ks * 16 + (lane & 3) * 2;

    const float* p = W + (size_t)e_lo * 2048 + k;
    float2 f0 = *(const float2*)p;               // (e_lo, k)    -> reg x
    float2 f1 = *(const float2*)(p + 8);         // (e_lo, k+8)  -> reg y
    float2 f2 = *(const float2*)(p + 8 * 2048);  // (e_hi, k)    -> reg z
    float2 f3 = *(const float2*)(p + 8 * 2048 + 8); // (e_hi, k+8) -> reg w

    uint4 q1, q2, q3;
    split2(f0, q1.x, q2.x, q3.x);
    split2(f1, q1.y, q2.y, q3.y);
    split2(f2, q1.z, q2.z, q3.z);
    split2(f3, q1.w, q2.w, q3.w);
    g_Bf[((ks * 3 + 0) * 4 + j) * 32 + lane] = q1;
    g_Bf[((ks * 3 + 1) * 4 + j) * 32 + lane] = q2;
    g_Bf[((ks * 3 + 2) * 4 + j) * 32 + lane] = q3;
}

__global__ __launch_bounds__(128, 2) void moe_gate_mma(
    const float* __restrict__ X,
    const float* __restrict__ bias,
    float* __restrict__ out,
    int w_off)
{
    __shared__ float Cs[64][65];

    const int tid  = threadIdx.x;
    const int lane = tid & 31;
    const int wid  = tid >> 5;           // 0..3
    const int wr   = wid >> 1;           // M strip (32 tokens)
    const int wc   = wid & 1;            // N half (32 experts)
    const int tok0 = blockIdx.x * 64;

    const float* aP0 = X + (size_t)(tok0 + wr * 32 + (lane >> 2)) * 2048
                         + (lane & 3) * 2;
    const float* aP1 = aP0 + (size_t)16 * 2048;      // second m-tile
    const uint4* bP  = g_Bf + 2 * wc * 32 + lane;

    float s_[2][4][4], cr[2][4][4];
    #pragma unroll
    for (int mt = 0; mt < 2; ++mt)
        #pragma unroll
        for (int nt = 0; nt < 4; ++nt)
            #pragma unroll
            for (int i = 0; i < 4; ++i) { s_[mt][nt][i] = 0.0f; cr[mt][nt][i] = 0.0f; }

    // current-iteration raw operands (prefetched)
    float2 Ac[8];
    uint4  Bc[6];
    #pragma unroll
    for (int r = 0; r < 4; ++r) {
        const float* p0 = aP0 + ((r & 1) ? (size_t)8 * 2048 : 0) + ((r >> 1) ? 8 : 0);
        const float* p1 = aP1 + ((r & 1) ? (size_t)8 * 2048 : 0) + ((r >> 1) ? 8 : 0);
        Ac[r]     = *(const float2*)p0;
        Ac[4 + r] = *(const float2*)p1;
    }
    #pragma unroll
    for (int t = 0; t < 3; ++t) {
        Bc[t * 2]     = bP[t * 128];
        Bc[t * 2 + 1] = bP[t * 128 + 32];
    }

    #pragma unroll 1
    for (int kb = 0; kb < 32; ++kb) {
        #pragma unroll
        for (int u = 0; u < 4; ++u) {
            const int ks = kb * 4 + u;
            const int kn = (ks + 1 < 128) ? ks + 1 : 127;   // clamped prefetch
            float2 An[8];
            uint4  Bn[6];
            #pragma unroll
            for (int r = 0; r < 4; ++r) {
                const size_t o = (size_t)kn * 16 + ((r & 1) ? (size_t)8 * 2048 : 0)
                                 + ((r >> 1) ? 8 : 0);
                An[r]     = *(const float2*)(aP0 + o);
                An[4 + r] = *(const float2*)(aP1 + o);
            }
            #pragma unroll
            for (int t = 0; t < 3; ++t) {
                Bn[t * 2]     = bP[(kn * 3 + t) * 128];
                Bn[t * 2 + 1] = bP[(kn * 3 + t) * 128 + 32];
            }

            // split current A into 3-term fragments
            uint32_t af[2][3][4];
            #pragma unroll
            for (int mt = 0; mt < 2; ++mt)
                #pragma unroll
                for (int r = 0; r < 4; ++r)
                    split2(Ac[mt * 4 + r], af[mt][0][r], af[mt][1][r], af[mt][2][r]);

            // 6 combos (sa + t <= 2), all into cr
            #pragma unroll
            for (int t = 0; t < 3; ++t)
                #pragma unroll
                for (int sa = 0; sa < 3; ++sa)
                    if (sa + t < 3) {
                        #pragma unroll
                        for (int mt = 0; mt < 2; ++mt) {
                            MMA16816(cr[mt][0], af[mt][sa], Bc[t * 2].x, Bc[t * 2].y);
                            MMA16816(cr[mt][1], af[mt][sa], Bc[t * 2].z, Bc[t * 2].w);
                            MMA16816(cr[mt][2], af[mt][sa], Bc[t * 2 + 1].x, Bc[t * 2 + 1].y);
                            MMA16816(cr[mt][3], af[mt][sa], Bc[t * 2 + 1].z, Bc[t * 2 + 1].w);
                        }
                    }

            #pragma unroll
            for (int r = 0; r < 8; ++r) Ac[r] = An[r];
            #pragma unroll
            for (int t = 0; t < 6; ++t) Bc[t] = Bn[t];
        }
        // 2Sum fold: cr -> s_, residue stays in cr
        #pragma unroll
        for (int mt = 0; mt < 2; ++mt)
            #pragma unroll
            for (int nt = 0; nt < 4; ++nt)
                #pragma unroll
                for (int i = 0; i < 4; ++i) {
                    float a = s_[mt][nt][i], b = cr[mt][nt][i];
                    float t1 = a + b;
                    float z  = t1 - a;
                    float e  = (a - (t1 - z)) + (b - z);
                    s_[mt][nt][i] = t1;
                    cr[mt][nt][i] = e;
                }
    }

    // ---- stage logits ----
    #pragma unroll
    for (int mt = 0; mt < 2; ++mt)
        #pragma unroll
        for (int nt = 0; nt < 4; ++nt) {
            const int r  = wr * 32 + mt * 16 + (lane >> 2);
            const int c0 = wc * 32 + nt * 8 + (lane & 3) * 2;
            Cs[r][c0]         = s_[mt][nt][0] + cr[mt][nt][0];
            Cs[r][c0 + 1]     = s_[mt][nt][1] + cr[mt][nt][1];
            Cs[r + 8][c0]     = s_[mt][nt][2] + cr[mt][nt][2];
            Cs[r + 8][c0 + 1] = s_[mt][nt][3] + cr[mt][nt][3];
        }
    __syncthreads();

    // ---- top-8 per token via REDUX; each warp handles 16 tokens ----
    const float blo = bias[lane];
    const float bhi = bias[lane + 32];

    #pragma unroll 1
    for (int tt = 0; tt < 16; ++tt) {
        const int m   = wid * 16 + tt;
        const int tok = tok0 + m;
        const float v0 = Cs[m][lane];
        const float v1 = Cs[m][lane + 32];
        unsigned c0 = __float_as_uint(v0 + blo);
        unsigned c1 = __float_as_uint(v1 + bhi);
        unsigned u0 = c0 ^ (((int)c0 >> 31) | 0x80000000u);
        unsigned u1 = c1 ^ (((int)c1 >> 31) | 0x80000000u);

        int sel_i = 0;
        #pragma unroll
        for (int k = 0; k < 8; ++k) {
            unsigned cu; int ci;
            if (u1 > u0) { cu = u1; ci = lane + 32; }
            else         { cu = u0; ci = lane; }
            unsigned mx = __reduce_max_sync(0xffffffffu, cu);
            unsigned cand = (cu == mx) ? (unsigned)ci : 1000u;
            int wi = (int)__reduce_min_sync(0xffffffffu, cand);
            if (lane == k) sel_i = wi;
            if (wi < 32) { if (lane == wi)      u0 = 0u; }
            else         { if (lane == wi - 32) u1 = 0u; }
        }

        float p = 0.0f;
        if (lane < 8) {
            float raw = Cs[m][sel_i];
            p = 1.0f / (1.0f + __expf(-raw));
        }
        float s = p;
        #pragma unroll
        for (int off = 4; off; off >>= 1) s += __shfl_xor_sync(0xffffffffu, s, off);
        s = fmaxf(s, 1e-12f);

        if (lane < 8) {
            out[(size_t)tok * 8 + lane]         = (float)sel_i;
            out[(size_t)w_off + tok * 8 + lane] = p / s;
        }
    }
}

extern "C" void kernel_launch(void* const* d_in, const int* in_sizes, int n_in,
                              void* d_out, int out_size) {
    const float* X    = (const float*)d_in[0];
    const float* W    = (const float*)d_in[1];
    const float* bias = (const float*)d_in[2];
    float* out = (float*)d_out;

    const int T = in_sizes[0] / 2048;   // 16384 tokens
    const int w_off = out_size >> 1;

    w_split_kernel<<<64, 256>>>(W);
    moe_gate_mma<<<T / 64, 128>>>(X, bias, out, w_off);
}

// round 10
// speedup vs baseline: 1.1284x; 1.1284x over previous
#include <cuda_runtime.h>
#include <cuda_bf16.h>
#include <cstdint>

// R10 hybrid: A via smem (split shared per CTA, LDSM), B via pre-permuted
// fragment LDG (g_Bf, L2-resident; no B smem). M=32/warp so B loads amortize.
// CTA 64 tok x 64 exp, 128 thr (2M x 2N warps), grid 256. rn 3-term split,
// 6 combos -> cr, 2Sum fold to s_ every 2 chunks. Output: [T*8 idx | T*8 w].

#define MMA16816(d, a, b0, b1)                                                \
    asm volatile("mma.sync.aligned.m16n8k16.row.col.f32.bf16.bf16.f32 "       \
                 "{%0,%1,%2,%3}, {%4,%5,%6,%7}, {%8,%9}, {%0,%1,%2,%3};"      \
                 : "+f"((d)[0]), "+f"((d)[1]), "+f"((d)[2]), "+f"((d)[3])     \
                 : "r"((a)[0]), "r"((a)[1]), "r"((a)[2]), "r"((a)[3]),        \
                   "r"(b0), "r"(b1))

#define LDSM4(r0, r1, r2, r3, addr)                                           \
    asm volatile("ldmatrix.sync.aligned.m8n8.x4.shared.b16 {%0,%1,%2,%3}, [%4];" \
                 : "=r"(r0), "=r"(r1), "=r"(r2), "=r"(r3) : "r"(addr))

// pack two f32 -> bf16x2 (lo in low half)
#define CVTPK(d, lo, hi)                                                      \
    asm("cvt.rn.bf16x2.f32 %0, %1, %2;" : "=r"(d) : "f"(hi), "f"(lo))

// B fragments: [ks(128)][term(3)][npair(4)][lane(32)] x uint4 = 786 KB
__device__ __align__(16) uint4 g_Bf[128 * 3 * 4 * 32];

static __device__ __forceinline__ void splitpair(float lo, float hi,
                                                 uint32_t& o1, uint32_t& o2,
                                                 uint32_t& o3) {
    CVTPK(o1, lo, hi);
    float l1 = lo - __uint_as_float(o1 << 16);
    float h1 = hi - __uint_as_float(o1 & 0xFFFF0000u);
    CVTPK(o2, l1, h1);
    float l2 = l1 - __uint_as_float(o2 << 16);
    float h2 = h1 - __uint_as_float(o2 & 0xFFFF0000u);
    CVTPK(o3, l2, h2);
}

// ---- one-time W pre-permute into mma B-fragment layout (verified in R9) ----
static __device__ __forceinline__ void split1(float x, unsigned short& a,
                                              unsigned short& b, unsigned short& c) {
    __nv_bfloat16 t1 = __float2bfloat16(x);
    float r1 = x - __bfloat162float(t1);
    __nv_bfloat16 t2 = __float2bfloat16(r1);
    float r2 = r1 - __bfloat162float(t2);
    __nv_bfloat16 t3 = __float2bfloat16(r2);
    a = __bfloat16_as_ushort(t1);
    b = __bfloat16_as_ushort(t2);
    c = __bfloat16_as_ushort(t3);
}
static __device__ __forceinline__ void split2w(float2 v, uint32_t& o1,
                                               uint32_t& o2, uint32_t& o3) {
    unsigned short ax, bx, cx, ay, by, cy;
    split1(v.x, ax, bx, cx);
    split1(v.y, ay, by, cy);
    o1 = (uint32_t)ax | ((uint32_t)ay << 16);
    o2 = (uint32_t)bx | ((uint32_t)by << 16);
    o3 = (uint32_t)cx | ((uint32_t)cy << 16);
}

__global__ void w_split_kernel(const float* __restrict__ W) {
    int idx  = blockIdx.x * 256 + threadIdx.x;   // 0..16383
    int lane = idx & 31;
    int j    = (idx >> 5) & 3;                   // npair: experts j*16..j*16+15
    int ks   = idx >> 7;                         // k16 step 0..127
    int e_lo = j * 16 + (lane >> 2);
    int k    = ks * 16 + (lane & 3) * 2;

    const float* p = W + (size_t)e_lo * 2048 + k;
    float2 f0 = *(const float2*)p;
    float2 f1 = *(const float2*)(p + 8);
    float2 f2 = *(const float2*)(p + 8 * 2048);
    float2 f3 = *(const float2*)(p + 8 * 2048 + 8);

    uint4 q1, q2, q3;
    split2w(f0, q1.x, q2.x, q3.x);
    split2w(f1, q1.y, q2.y, q3.y);
    split2w(f2, q1.z, q2.z, q3.z);
    split2w(f3, q1.w, q2.w, q3.w);
    g_Bf[((ks * 3 + 0) * 4 + j) * 32 + lane] = q1;
    g_Bf[((ks * 3 + 1) * 4 + j) * 32 + lane] = q2;
    g_Bf[((ks * 3 + 2) * 4 + j) * 32 + lane] = q3;
}

// ---- main kernel ----
// smem: A tiles [buf(2)][term(3)][64 rows x 80B] = 30720 B; Cs overlays it.
#define TERM_BT 5120
#define BUF_BT  15360

__global__ __launch_bounds__(128, 2) void moe_gate_mma(
    const float* __restrict__ X,
    const float* __restrict__ bias,
    float* __restrict__ out,
    int w_off)
{
    __shared__ union {
        char  tiles[2 * BUF_BT];
        float Cs[64][65];
    } sm;

    const int tid  = threadIdx.x;
    const int lane = tid & 31;
    const int wid  = tid >> 5;           // 0..3
    const int wr   = wid >> 1;           // M strip (32 tokens)
    const int wc   = wid & 1;            // N half (32 experts)
    const int tok0 = blockIdx.x * 64;

    uint32_t sb;
    asm("{ .reg .u64 t; cvta.to.shared.u64 t, %1; cvt.u32.u64 %0, t; }"
        : "=r"(sb) : "l"(sm.tiles));

    // A gmem loader: row = tid>>1 (0..63), k-half = (tid&1)*16
    const int arow = tid >> 1;
    const int akh  = (tid & 1) * 16;
    const float* aP = X + (size_t)(tok0 + arow) * 2048 + akh;
    const int stOff = arow * 80 + akh * 2;          // byte offset in a term tile

    // B fragment pointer (R9-verified layout)
    const uint4* bP = g_Bf + 2 * wc * 32 + lane;

    // A LDSM lane offsets
    const int a_r  = (lane & 7) + ((lane >> 3) & 1) * 8;   // row within m-tile
    const int a_kb = ((lane >> 4) & 1) * 16;               // k byte offset

    float s_[2][4][4], cr[2][4][4];
    #pragma unroll
    for (int mt = 0; mt < 2; ++mt)
        #pragma unroll
        for (int nt = 0; nt < 4; ++nt)
            #pragma unroll
            for (int i = 0; i < 4; ++i) { s_[mt][nt][i] = 0.0f; cr[mt][nt][i] = 0.0f; }

    // ---- chunk 0: load + split + store buf 0 ----
    {
        float4 p0 = *(const float4*)(aP);
        float4 p1 = *(const float4*)(aP + 4);
        float4 p2 = *(const float4*)(aP + 8);
        float4 p3 = *(const float4*)(aP + 12);
        uint32_t o1[8], o2[8], o3[8];
        splitpair(p0.x, p0.y, o1[0], o2[0], o3[0]);
        splitpair(p0.z, p0.w, o1[1], o2[1], o3[1]);
        splitpair(p1.x, p1.y, o1[2], o2[2], o3[2]);
        splitpair(p1.z, p1.w, o1[3], o2[3], o3[3]);
        splitpair(p2.x, p2.y, o1[4], o2[4], o3[4]);
        splitpair(p2.z, p2.w, o1[5], o2[5], o3[5]);
        splitpair(p3.x, p3.y, o1[6], o2[6], o3[6]);
        splitpair(p3.z, p3.w, o1[7], o2[7], o3[7]);
        char* b0 = sm.tiles + stOff;
        *(uint4*)(b0)                    = make_uint4(o1[0], o1[1], o1[2], o1[3]);
        *(uint4*)(b0 + 16)               = make_uint4(o1[4], o1[5], o1[6], o1[7]);
        *(uint4*)(b0 + TERM_BT)          = make_uint4(o2[0], o2[1], o2[2], o2[3]);
        *(uint4*)(b0 + TERM_BT + 16)     = make_uint4(o2[4], o2[5], o2[6], o2[7]);
        *(uint4*)(b0 + 2 * TERM_BT)      = make_uint4(o3[0], o3[1], o3[2], o3[3]);
        *(uint4*)(b0 + 2 * TERM_BT + 16) = make_uint4(o3[4], o3[5], o3[6], o3[7]);
    }
    // initial B fragments (ksg = 0)
    uint4 Bc[6];
    #pragma unroll
    for (int t = 0; t < 3; ++t) {
        Bc[t * 2]     = bP[t * 128];
        Bc[t * 2 + 1] = bP[t * 128 + 32];
    }
    __syncthreads();

    float4 pa0, pa1, pa2, pa3;
    #pragma unroll 1
    for (int c = 0; c < 64; ++c) {
        const int cur = c & 1;
        if (c < 63) {                             // prefetch A chunk c+1
            const int o = (c + 1) * 32;
            pa0 = *(const float4*)(aP + o);
            pa1 = *(const float4*)(aP + o + 4);
            pa2 = *(const float4*)(aP + o + 8);
            pa3 = *(const float4*)(aP + o + 12);
        }
        #pragma unroll
        for (int ks = 0; ks < 2; ++ks) {
            // prefetch next B fragment set
            const int kn = (2 * c + ks + 1 < 128) ? 2 * c + ks + 1 : 127;
            uint4 Bn[6];
            #pragma unroll
            for (int t = 0; t < 3; ++t) {
                Bn[t * 2]     = bP[(kn * 3 + t) * 128];
                Bn[t * 2 + 1] = bP[(kn * 3 + t) * 128 + 32];
            }
            // A fragments: 2 m-tiles x 3 terms
            uint32_t af[2][3][4];
            #pragma unroll
            for (int mt = 0; mt < 2; ++mt)
                #pragma unroll
                for (int t = 0; t < 3; ++t) {
                    uint32_t ad = sb + cur * BUF_BT + t * TERM_BT
                                + (wr * 32 + mt * 16 + a_r) * 80 + a_kb + ks * 32;
                    LDSM4(af[mt][t][0], af[mt][t][1], af[mt][t][2], af[mt][t][3], ad);
                }
            // 6 combos (sa + t <= 2), all into cr
            #pragma unroll
            for (int t = 0; t < 3; ++t)
                #pragma unroll
                for (int sa = 0; sa < 3; ++sa)
                    if (sa + t < 3) {
                        #pragma unroll
                        for (int mt = 0; mt < 2; ++mt) {
                            MMA16816(cr[mt][0], af[mt][sa], Bc[t * 2].x, Bc[t * 2].y);
                            MMA16816(cr[mt][1], af[mt][sa], Bc[t * 2].z, Bc[t * 2].w);
                            MMA16816(cr[mt][2], af[mt][sa], Bc[t * 2 + 1].x, Bc[t * 2 + 1].y);
                            MMA16816(cr[mt][3], af[mt][sa], Bc[t * 2 + 1].z, Bc[t * 2 + 1].w);
                        }
                    }
            #pragma unroll
            for (int t = 0; t < 6; ++t) Bc[t] = Bn[t];
        }
        if (c & 1) {                              // 2Sum fold every 2 chunks
            #pragma unroll
            for (int mt = 0; mt < 2; ++mt)
                #pragma unroll
                for (int nt = 0; nt < 4; ++nt)
                    #pragma unroll
                    for (int i = 0; i < 4; ++i) {
                        float a = s_[mt][nt][i], b = cr[mt][nt][i];
                        float t1 = a + b;
                        float z  = t1 - a;
                        float e  = (a - (t1 - z)) + (b - z);
                        s_[mt][nt][i] = t1;
                        cr[mt][nt][i] = e;
                    }
        }
        if (c < 63) {                             // split + store buf nxt
            uint32_t o1[8], o2[8], o3[8];
            splitpair(pa0.x, pa0.y, o1[0], o2[0], o3[0]);
            splitpair(pa0.z, pa0.w, o1[1], o2[1], o3[1]);
            splitpair(pa1.x, pa1.y, o1[2], o2[2], o3[2]);
            splitpair(pa1.z, pa1.w, o1[3], o2[3], o3[3]);
            splitpair(pa2.x, pa2.y, o1[4], o2[4], o3[4]);
            splitpair(pa2.z, pa2.w, o1[5], o2[5], o3[5]);
            splitpair(pa3.x, pa3.y, o1[6], o2[6], o3[6]);
            splitpair(pa3.z, pa3.w, o1[7], o2[7], o3[7]);
            char* b0 = sm.tiles + (cur ^ 1) * BUF_BT + stOff;
            *(uint4*)(b0)                    = make_uint4(o1[0], o1[1], o1[2], o1[3]);
            *(uint4*)(b0 + 16)               = make_uint4(o1[4], o1[5], o1[6], o1[7]);
            *(uint4*)(b0 + TERM_BT)          = make_uint4(o2[0], o2[1], o2[2], o2[3]);
            *(uint4*)(b0 + TERM_BT + 16)     = make_uint4(o2[4], o2[5], o2[6], o2[7]);
            *(uint4*)(b0 + 2 * TERM_BT)      = make_uint4(o3[0], o3[1], o3[2], o3[3]);
            *(uint4*)(b0 + 2 * TERM_BT + 16) = make_uint4(o3[4], o3[5], o3[6], o3[7]);
        }
        __syncthreads();
    }

    // ---- stage logits into Cs (overlays tiles; mainloop ended with sync) ----
    #pragma unroll
    for (int mt = 0; mt < 2; ++mt)
        #pragma unroll
        for (int nt = 0; nt < 4; ++nt) {
            const int r  = wr * 32 + mt * 16 + (lane >> 2);
            const int c0 = wc * 32 + nt * 8 + (lane & 3) * 2;
            sm.Cs[r][c0]         = s_[mt][nt][0] + cr[mt][nt][0];
            sm.Cs[r][c0 + 1]     = s_[mt][nt][1] + cr[mt][nt][1];
            sm.Cs[r + 8][c0]     = s_[mt][nt][2] + cr[mt][nt][2];
            sm.Cs[r + 8][c0 + 1] = s_[mt][nt][3] + cr[mt][nt][3];
        }
    __syncthreads();

    // ---- top-8 per token via REDUX; each warp handles 16 tokens ----
    const float blo = bias[lane];
    const float bhi = bias[lane + 32];

    #pragma unroll 1
    for (int tt = 0; tt < 16; ++tt) {
        const int m   = wid * 16 + tt;
        const int tok = tok0 + m;
        const float v0 = sm.Cs[m][lane];
        const float v1 = sm.Cs[m][lane + 32];
        unsigned c0 = __float_as_uint(v0 + blo);
        unsigned c1 = __float_as_uint(v1 + bhi);
        unsigned u0 = c0 ^ (((int)c0 >> 31) | 0x80000000u);
        unsigned u1 = c1 ^ (((int)c1 >> 31) | 0x80000000u);

        int sel_i = 0;
        #pragma unroll
        for (int k = 0; k < 8; ++k) {
            unsigned cu; int ci;
            if (u1 > u0) { cu = u1; ci = lane + 32; }
            else         { cu = u0; ci = lane; }
            unsigned mx = __reduce_max_sync(0xffffffffu, cu);
            unsigned cand = (cu == mx) ? (unsigned)ci : 1000u;
            int wi = (int)__reduce_min_sync(0xffffffffu, cand);
            if (lane == k) sel_i = wi;
            if (wi < 32) { if (lane == wi)      u0 = 0u; }
            else         { if (lane == wi - 32) u1 = 0u; }
        }

        float p = 0.0f;
        if (lane < 8) {
            float raw = sm.Cs[m][sel_i];
            p = 1.0f / (1.0f + __expf(-raw));
        }
        float s = p;
        #pragma unroll
        for (int off = 4; off; off >>= 1) s += __shfl_xor_sync(0xffffffffu, s, off);
        s = fmaxf(s, 1e-12f);

        if (lane < 8) {
            out[(size_t)tok * 8 + lane]         = (float)sel_i;
            out[(size_t)w_off + tok * 8 + lane] = p / s;
        }
    }
}

extern "C" void kernel_launch(void* const* d_in, const int* in_sizes, int n_in,
                              void* d_out, int out_size) {
    const float* X    = (const float*)d_in[0];
    const float* W    = (const float*)d_in[1];
    const float* bias = (const float*)d_in[2];
    float* out = (float*)d_out;

    const int T = in_sizes[0] / 2048;   // 16384 tokens
    const int w_off = out_size >> 1;

    w_split_kernel<<<64, 256>>>(W);
    moe_gate_mma<<<T / 64, 128>>>(X, bias, out, w_off);
}

// round 11
// speedup vs baseline: 1.3744x; 1.2180x over previous
#include <cuda_runtime.h>
#include <cuda_fp16.h>
#include <cstdint>

// R11: fp16 2-term split, 3 MMA combos (halves tensor+L1 work vs 6x bf16).
// h1g1 -> per-chunk partial dm, Fast2Sum fold into s_ (residue->cr);
// h1g2 + h2g1 (2^-11 scale) -> cr. Dropped h2g2 ~2^-22. Logit err ~4e-7.
// A via smem (split shared per CTA, LDSM); B pre-permuted fp16 fragments in
// gmem (L2-resident), LDG.128 direct to regs. CTA 64 tok x 64 exp, 128 thr.
// Output: [T*8 idx as float | T*8 weights].

#define MMAH(d, a, b0, b1)                                                    \
    asm volatile("mma.sync.aligned.m16n8k16.row.col.f32.f16.f16.f32 "         \
                 "{%0,%1,%2,%3}, {%4,%5,%6,%7}, {%8,%9}, {%0,%1,%2,%3};"      \
                 : "+f"((d)[0]), "+f"((d)[1]), "+f"((d)[2]), "+f"((d)[3])     \
                 : "r"((a)[0]), "r"((a)[1]), "r"((a)[2]), "r"((a)[3]),        \
                   "r"(b0), "r"(b1))

#define LDSM4(r0, r1, r2, r3, addr)                                           \
    asm volatile("ldmatrix.sync.aligned.m8n8.x4.shared.b16 {%0,%1,%2,%3}, [%4];" \
                 : "=r"(r0), "=r"(r1), "=r"(r2), "=r"(r3) : "r"(addr))

// pack two f32 -> f16x2 (lo in low half)
#define CVTPKH(d, lo, hi)                                                     \
    asm("cvt.rn.f16x2.f32 %0, %1, %2;" : "=r"(d) : "f"(hi), "f"(lo))

// B fragments: [ks(128)][term(2)][npair(4)][lane(32)] x uint4 = 512 KB
__device__ __align__(16) uint4 g_Bf[128 * 2 * 4 * 32];

static __device__ __forceinline__ void splitpairh(float lo, float hi,
                                                  uint32_t& o1, uint32_t& o2) {
    CVTPKH(o1, lo, hi);
    __half2 h = *reinterpret_cast<__half2*>(&o1);
    float2 b = __half22float2(h);
    float l1 = lo - b.x;
    float h1 = hi - b.y;
    CVTPKH(o2, l1, h1);
}

__global__ void w_split_kernel(const float* __restrict__ W) {
    int idx  = blockIdx.x * 256 + threadIdx.x;   // 0..16383
    int lane = idx & 31;
    int j    = (idx >> 5) & 3;                   // npair: experts j*16..j*16+15
    int ks   = idx >> 7;                         // k16 step 0..127
    int e_lo = j * 16 + (lane >> 2);
    int k    = ks * 16 + (lane & 3) * 2;

    const float* p = W + (size_t)e_lo * 2048 + k;
    float2 f0 = *(const float2*)p;               // (e_lo, k)
    float2 f1 = *(const float2*)(p + 8);         // (e_lo, k+8)
    float2 f2 = *(const float2*)(p + 8 * 2048);  // (e_hi, k)
    float2 f3 = *(const float2*)(p + 8 * 2048 + 8);

    uint4 q1, q2;
    splitpairh(f0.x, f0.y, q1.x, q2.x);
    splitpairh(f1.x, f1.y, q1.y, q2.y);
    splitpairh(f2.x, f2.y, q1.z, q2.z);
    splitpairh(f3.x, f3.y, q1.w, q2.w);
    g_Bf[((ks * 2 + 0) * 4 + j) * 32 + lane] = q1;
    g_Bf[((ks * 2 + 1) * 4 + j) * 32 + lane] = q2;
}

// smem: A tiles [buf(2)][term(2)][64 rows x 80B] = 20480 B; Cs overlays it.
#define TERM_BT 5120
#define BUF_BT  10240

__global__ __launch_bounds__(128, 2) void moe_gate_mma(
    const float* __restrict__ X,
    const float* __restrict__ bias,
    float* __restrict__ out,
    int w_off)
{
    __shared__ union {
        char  tiles[2 * BUF_BT];
        float Cs[64][65];
    } sm;

    const int tid  = threadIdx.x;
    const int lane = tid & 31;
    const int wid  = tid >> 5;           // 0..3
    const int wr   = wid >> 1;           // M strip (32 tokens)
    const int wc   = wid & 1;            // N half (32 experts)
    const int tok0 = blockIdx.x * 64;

    uint32_t sb;
    asm("{ .reg .u64 t; cvta.to.shared.u64 t, %1; cvt.u32.u64 %0, t; }"
        : "=r"(sb) : "l"(sm.tiles));

    // A gmem loader: row = tid>>1 (0..63), k-half = (tid&1)*16
    const int arow = tid >> 1;
    const int akh  = (tid & 1) * 16;
    const float* aP = X + (size_t)(tok0 + arow) * 2048 + akh;
    const int stOff = arow * 80 + akh * 2;          // byte offset in a term tile

    // B fragment pointer
    const uint4* bP = g_Bf + 2 * wc * 32 + lane;

    // A LDSM lane offsets
    const int a_r  = (lane & 7) + ((lane >> 3) & 1) * 8;
    const int a_kb = ((lane >> 4) & 1) * 16;

    float s_[2][4][4], cr[2][4][4], dm[2][4][4];
    #pragma unroll
    for (int mt = 0; mt < 2; ++mt)
        #pragma unroll
        for (int nt = 0; nt < 4; ++nt)
            #pragma unroll
            for (int i = 0; i < 4; ++i) { s_[mt][nt][i] = 0.0f; cr[mt][nt][i] = 0.0f; }

    // ---- chunk 0: load + split + store buf 0 ----
    {
        float4 p0 = *(const float4*)(aP);
        float4 p1 = *(const float4*)(aP + 4);
        float4 p2 = *(const float4*)(aP + 8);
        float4 p3 = *(const float4*)(aP + 12);
        uint32_t o1[8], o2[8];
        splitpairh(p0.x, p0.y, o1[0], o2[0]);
        splitpairh(p0.z, p0.w, o1[1], o2[1]);
        splitpairh(p1.x, p1.y, o1[2], o2[2]);
        splitpairh(p1.z, p1.w, o1[3], o2[3]);
        splitpairh(p2.x, p2.y, o1[4], o2[4]);
        splitpairh(p2.z, p2.w, o1[5], o2[5]);
        splitpairh(p3.x, p3.y, o1[6], o2[6]);
        splitpairh(p3.z, p3.w, o1[7], o2[7]);
        char* b0 = sm.tiles + stOff;
        *(uint4*)(b0)                = make_uint4(o1[0], o1[1], o1[2], o1[3]);
        *(uint4*)(b0 + 16)           = make_uint4(o1[4], o1[5], o1[6], o1[7]);
        *(uint4*)(b0 + TERM_BT)      = make_uint4(o2[0], o2[1], o2[2], o2[3]);
        *(uint4*)(b0 + TERM_BT + 16) = make_uint4(o2[4], o2[5], o2[6], o2[7]);
    }
    uint4 Bc[4];                                   // [term][jpair]
    #pragma unroll
    for (int t = 0; t < 2; ++t) {
        Bc[t * 2]     = bP[t * 128];
        Bc[t * 2 + 1] = bP[t * 128 + 32];
    }
    __syncthreads();

    float4 pa0, pa1, pa2, pa3;
    #pragma unroll 1
    for (int c = 0; c < 64; ++c) {
        const int cur = c & 1;
        if (c < 63) {                              // prefetch A chunk c+1
            const int o = (c + 1) * 32;
            pa0 = *(const float4*)(aP + o);
            pa1 = *(const float4*)(aP + o + 4);
            pa2 = *(const float4*)(aP + o + 8);
            pa3 = *(const float4*)(aP + o + 12);
        }
        // zero per-chunk main partial
        #pragma unroll
        for (int mt = 0; mt < 2; ++mt)
            #pragma unroll
            for (int nt = 0; nt < 4; ++nt)
                #pragma unroll
                for (int i = 0; i < 4; ++i) dm[mt][nt][i] = 0.0f;

        #pragma unroll
        for (int ks = 0; ks < 2; ++ks) {
            // prefetch next B fragment set
            const int kn = (2 * c + ks + 1 < 128) ? 2 * c + ks + 1 : 127;
            uint4 Bn[4];
            #pragma unroll
            for (int t = 0; t < 2; ++t) {
                Bn[t * 2]     = bP[(kn * 2 + t) * 128];
                Bn[t * 2 + 1] = bP[(kn * 2 + t) * 128 + 32];
            }
            // A fragments: 2 m-tiles x 2 terms
            uint32_t af[2][2][4];
            #pragma unroll
            for (int mt = 0; mt < 2; ++mt)
                #pragma unroll
                for (int t = 0; t < 2; ++t) {
                    uint32_t ad = sb + cur * BUF_BT + t * TERM_BT
                                + (wr * 32 + mt * 16 + a_r) * 80 + a_kb + ks * 32;
                    LDSM4(af[mt][t][0], af[mt][t][1], af[mt][t][2], af[mt][t][3], ad);
                }
            // 3 combos: h1g1 -> dm; h1g2, h2g1 -> cr
            #pragma unroll
            for (int mt = 0; mt < 2; ++mt) {
                MMAH(dm[mt][0], af[mt][0], Bc[0].x, Bc[0].y);
                MMAH(dm[mt][1], af[mt][0], Bc[0].z, Bc[0].w);
                MMAH(dm[mt][2], af[mt][0], Bc[1].x, Bc[1].y);
                MMAH(dm[mt][3], af[mt][0], Bc[1].z, Bc[1].w);

                MMAH(cr[mt][0], af[mt][0], Bc[2].x, Bc[2].y);
                MMAH(cr[mt][1], af[mt][0], Bc[2].z, Bc[2].w);
                MMAH(cr[mt][2], af[mt][0], Bc[3].x, Bc[3].y);
                MMAH(cr[mt][3], af[mt][0], Bc[3].z, Bc[3].w);

                MMAH(cr[mt][0], af[mt][1], Bc[0].x, Bc[0].y);
                MMAH(cr[mt][1], af[mt][1], Bc[0].z, Bc[0].w);
                MMAH(cr[mt][2], af[mt][1], Bc[1].x, Bc[1].y);
                MMAH(cr[mt][3], af[mt][1], Bc[1].z, Bc[1].w);
            }
            #pragma unroll
            for (int t = 0; t < 4; ++t) Bc[t] = Bn[t];
        }
        // 2Sum fold: dm -> s_, residue -> cr
        #pragma unroll
        for (int mt = 0; mt < 2; ++mt)
            #pragma unroll
            for (int nt = 0; nt < 4; ++nt)
                #pragma unroll
                for (int i = 0; i < 4; ++i) {
                    float a = s_[mt][nt][i], b = dm[mt][nt][i];
                    float t1 = a + b;
                    float z  = t1 - a;
                    float e  = (a - (t1 - z)) + (b - z);
                    s_[mt][nt][i] = t1;
                    cr[mt][nt][i] += e;
                }

        if (c < 63) {                              // split + store buf nxt
            uint32_t o1[8], o2[8];
            splitpairh(pa0.x, pa0.y, o1[0], o2[0]);
            splitpairh(pa0.z, pa0.w, o1[1], o2[1]);
            splitpairh(pa1.x, pa1.y, o1[2], o2[2]);
            splitpairh(pa1.z, pa1.w, o1[3], o2[3]);
            splitpairh(pa2.x, pa2.y, o1[4], o2[4]);
            splitpairh(pa2.z, pa2.w, o1[5], o2[5]);
            splitpairh(pa3.x, pa3.y, o1[6], o2[6]);
            splitpairh(pa3.z, pa3.w, o1[7], o2[7]);
            char* b0 = sm.tiles + (cur ^ 1) * BUF_BT + stOff;
            *(uint4*)(b0)                = make_uint4(o1[0], o1[1], o1[2], o1[3]);
            *(uint4*)(b0 + 16)           = make_uint4(o1[4], o1[5], o1[6], o1[7]);
            *(uint4*)(b0 + TERM_BT)      = make_uint4(o2[0], o2[1], o2[2], o2[3]);
            *(uint4*)(b0 + TERM_BT + 16) = make_uint4(o2[4], o2[5], o2[6], o2[7]);
        }
        __syncthreads();
    }

    // ---- stage logits into Cs ----
    #pragma unroll
    for (int mt = 0; mt < 2; ++mt)
        #pragma unroll
        for (int nt = 0; nt < 4; ++nt) {
            const int r  = wr * 32 + mt * 16 + (lane >> 2);
            const int c0 = wc * 32 + nt * 8 + (lane & 3) * 2;
            sm.Cs[r][c0]         = s_[mt][nt][0] + cr[mt][nt][0];
            sm.Cs[r][c0 + 1]     = s_[mt][nt][1] + cr[mt][nt][1];
            sm.Cs[r + 8][c0]     = s_[mt][nt][2] + cr[mt][nt][2];
            sm.Cs[r + 8][c0 + 1] = s_[mt][nt][3] + cr[mt][nt][3];
        }
    __syncthreads();

    // ---- top-8 per token via REDUX; each warp handles 16 tokens ----
    const float blo = bias[lane];
    const float bhi = bias[lane + 32];

    #pragma unroll 1
    for (int tt = 0; tt < 16; ++tt) {
        const int m   = wid * 16 + tt;
        const int tok = tok0 + m;
        const float v0 = sm.Cs[m][lane];
        const float v1 = sm.Cs[m][lane + 32];
        unsigned c0 = __float_as_uint(v0 + blo);
        unsigned c1 = __float_as_uint(v1 + bhi);
        unsigned u0 = c0 ^ (((int)c0 >> 31) | 0x80000000u);
        unsigned u1 = c1 ^ (((int)c1 >> 31) | 0x80000000u);

        int sel_i = 0;
        #pragma unroll
        for (int k = 0; k < 8; ++k) {
            unsigned cu; int ci;
            if (u1 > u0) { cu = u1; ci = lane + 32; }
            else         { cu = u0; ci = lane; }
            unsigned mx = __reduce_max_sync(0xffffffffu, cu);
            unsigned cand = (cu == mx) ? (unsigned)ci : 1000u;
            int wi = (int)__reduce_min_sync(0xffffffffu, cand);
            if (lane == k) sel_i = wi;
            if (wi < 32) { if (lane == wi)      u0 = 0u; }
            else         { if (lane == wi - 32) u1 = 0u; }
        }

        float p = 0.0f;
        if (lane < 8) {
            float raw = sm.Cs[m][sel_i];
            p = 1.0f / (1.0f + __expf(-raw));
        }
        float s = p;
        #pragma unroll
        for (int off = 4; off; off >>= 1) s += __shfl_xor_sync(0xffffffffu, s, off);
        s = fmaxf(s, 1e-12f);

        if (lane < 8) {
            out[(size_t)tok * 8 + lane]         = (float)sel_i;
            out[(size_t)w_off + tok * 8 + lane] = p / s;
        }
    }
}

extern "C" void kernel_launch(void* const* d_in, const int* in_sizes, int n_in,
                              void* d_out, int out_size) {
    const float* X    = (const float*)d_in[0];
    const float* W    = (const float*)d_in[1];
    const float* bias = (const float*)d_in[2];
    float* out = (float*)d_out;

    const int T = in_sizes[0] / 2048;   // 16384 tokens
    const int w_off = out_size >> 1;

    w_split_kernel<<<64, 256>>>(W);
    moe_gate_mma<<<T / 64, 128>>>(X, bias, out, w_off);
}

// round 12
// speedup vs baseline: 1.4711x; 1.0704x over previous
#include <cuda_runtime.h>
#include <cuda_fp16.h>
#include <cstdint>

// R12: R11 (fp16 2-term split, 3 combos) with the fold bottleneck removed.
// All 3 combos accumulate into cr; 2Sum fold cr->s_ every 2 chunks (R10's
// proven structure). dm eliminated (-32 regs), launch_bounds(128,3) ->
// 12 warps/SM. Output: [T*8 idx as float | T*8 weights].

#define MMAH(d, a, b0, b1)                                                    \
    asm volatile("mma.sync.aligned.m16n8k16.row.col.f32.f16.f16.f32 "         \
                 "{%0,%1,%2,%3}, {%4,%5,%6,%7}, {%8,%9}, {%0,%1,%2,%3};"      \
                 : "+f"((d)[0]), "+f"((d)[1]), "+f"((d)[2]), "+f"((d)[3])     \
                 : "r"((a)[0]), "r"((a)[1]), "r"((a)[2]), "r"((a)[3]),        \
                   "r"(b0), "r"(b1))

#define LDSM4(r0, r1, r2, r3, addr)                                           \
    asm volatile("ldmatrix.sync.aligned.m8n8.x4.shared.b16 {%0,%1,%2,%3}, [%4];" \
                 : "=r"(r0), "=r"(r1), "=r"(r2), "=r"(r3) : "r"(addr))

// pack two f32 -> f16x2 (lo in low half)
#define CVTPKH(d, lo, hi)                                                     \
    asm("cvt.rn.f16x2.f32 %0, %1, %2;" : "=r"(d) : "f"(hi), "f"(lo))

// B fragments: [ks(128)][term(2)][npair(4)][lane(32)] x uint4 = 512 KB
__device__ __align__(16) uint4 g_Bf[128 * 2 * 4 * 32];

static __device__ __forceinline__ void splitpairh(float lo, float hi,
                                                  uint32_t& o1, uint32_t& o2) {
    CVTPKH(o1, lo, hi);
    __half2 h = *reinterpret_cast<__half2*>(&o1);
    float2 b = __half22float2(h);
    float l1 = lo - b.x;
    float h1 = hi - b.y;
    CVTPKH(o2, l1, h1);
}

__global__ void w_split_kernel(const float* __restrict__ W) {
    int idx  = blockIdx.x * 256 + threadIdx.x;   // 0..16383
    int lane = idx & 31;
    int j    = (idx >> 5) & 3;                   // npair: experts j*16..j*16+15
    int ks   = idx >> 7;                         // k16 step 0..127
    int e_lo = j * 16 + (lane >> 2);
    int k    = ks * 16 + (lane & 3) * 2;

    const float* p = W + (size_t)e_lo * 2048 + k;
    float2 f0 = *(const float2*)p;
    float2 f1 = *(const float2*)(p + 8);
    float2 f2 = *(const float2*)(p + 8 * 2048);
    float2 f3 = *(const float2*)(p + 8 * 2048 + 8);

    uint4 q1, q2;
    splitpairh(f0.x, f0.y, q1.x, q2.x);
    splitpairh(f1.x, f1.y, q1.y, q2.y);
    splitpairh(f2.x, f2.y, q1.z, q2.z);
    splitpairh(f3.x, f3.y, q1.w, q2.w);
    g_Bf[((ks * 2 + 0) * 4 + j) * 32 + lane] = q1;
    g_Bf[((ks * 2 + 1) * 4 + j) * 32 + lane] = q2;
}

// smem: A tiles [buf(2)][term(2)][64 rows x 80B] = 20480 B; Cs overlays it.
#define TERM_BT 5120
#define BUF_BT  10240

__global__ __launch_bounds__(128, 3) void moe_gate_mma(
    const float* __restrict__ X,
    const float* __restrict__ bias,
    float* __restrict__ out,
    int w_off)
{
    __shared__ union {
        char  tiles[2 * BUF_BT];
        float Cs[64][65];
    } sm;

    const int tid  = threadIdx.x;
    const int lane = tid & 31;
    const int wid  = tid >> 5;           // 0..3
    const int wr   = wid >> 1;           // M strip (32 tokens)
    const int wc   = wid & 1;            // N half (32 experts)
    const int tok0 = blockIdx.x * 64;

    uint32_t sb;
    asm("{ .reg .u64 t; cvta.to.shared.u64 t, %1; cvt.u32.u64 %0, t; }"
        : "=r"(sb) : "l"(sm.tiles));

    // A gmem loader: row = tid>>1 (0..63), k-half = (tid&1)*16
    const int arow = tid >> 1;
    const int akh  = (tid & 1) * 16;
    const float* aP = X + (size_t)(tok0 + arow) * 2048 + akh;
    const int stOff = arow * 80 + akh * 2;          // byte offset in a term tile

    // B fragment pointer
    const uint4* bP = g_Bf + 2 * wc * 32 + lane;

    // A LDSM lane offsets
    const int a_r  = (lane & 7) + ((lane >> 3) & 1) * 8;
    const int a_kb = ((lane >> 4) & 1) * 16;

    float s_[2][4][4], cr[2][4][4];
    #pragma unroll
    for (int mt = 0; mt < 2; ++mt)
        #pragma unroll
        for (int nt = 0; nt < 4; ++nt)
            #pragma unroll
            for (int i = 0; i < 4; ++i) { s_[mt][nt][i] = 0.0f; cr[mt][nt][i] = 0.0f; }

    // ---- chunk 0: load + split + store buf 0 ----
    {
        float4 p0 = *(const float4*)(aP);
        float4 p1 = *(const float4*)(aP + 4);
        float4 p2 = *(const float4*)(aP + 8);
        float4 p3 = *(const float4*)(aP + 12);
        uint32_t o1[8], o2[8];
        splitpairh(p0.x, p0.y, o1[0], o2[0]);
        splitpairh(p0.z, p0.w, o1[1], o2[1]);
        splitpairh(p1.x, p1.y, o1[2], o2[2]);
        splitpairh(p1.z, p1.w, o1[3], o2[3]);
        splitpairh(p2.x, p2.y, o1[4], o2[4]);
        splitpairh(p2.z, p2.w, o1[5], o2[5]);
        splitpairh(p3.x, p3.y, o1[6], o2[6]);
        splitpairh(p3.z, p3.w, o1[7], o2[7]);
        char* b0 = sm.tiles + stOff;
        *(uint4*)(b0)                = make_uint4(o1[0], o1[1], o1[2], o1[3]);
        *(uint4*)(b0 + 16)           = make_uint4(o1[4], o1[5], o1[6], o1[7]);
        *(uint4*)(b0 + TERM_BT)      = make_uint4(o2[0], o2[1], o2[2], o2[3]);
        *(uint4*)(b0 + TERM_BT + 16) = make_uint4(o2[4], o2[5], o2[6], o2[7]);
    }
    uint4 Bc[4];                                   // [term][jpair]
    #pragma unroll
    for (int t = 0; t < 2; ++t) {
        Bc[t * 2]     = bP[t * 128];
        Bc[t * 2 + 1] = bP[t * 128 + 32];
    }
    __syncthreads();

    float4 pa0, pa1, pa2, pa3;
    #pragma unroll 1
    for (int c = 0; c < 64; ++c) {
        const int cur = c & 1;
        if (c < 63) {                              // prefetch A chunk c+1
            const int o = (c + 1) * 32;
            pa0 = *(const float4*)(aP + o);
            pa1 = *(const float4*)(aP + o + 4);
            pa2 = *(const float4*)(aP + o + 8);
            pa3 = *(const float4*)(aP + o + 12);
        }
        #pragma unroll
        for (int ks = 0; ks < 2; ++ks) {
            // prefetch next B fragment set
            const int kn = (2 * c + ks + 1 < 128) ? 2 * c + ks + 1 : 127;
            uint4 Bn[4];
            #pragma unroll
            for (int t = 0; t < 2; ++t) {
                Bn[t * 2]     = bP[(kn * 2 + t) * 128];
                Bn[t * 2 + 1] = bP[(kn * 2 + t) * 128 + 32];
            }
            // A fragments: 2 m-tiles x 2 terms
            uint32_t af[2][2][4];
            #pragma unroll
            for (int mt = 0; mt < 2; ++mt)
                #pragma unroll
                for (int t = 0; t < 2; ++t) {
                    uint32_t ad = sb + cur * BUF_BT + t * TERM_BT
                                + (wr * 32 + mt * 16 + a_r) * 80 + a_kb + ks * 32;
                    LDSM4(af[mt][t][0], af[mt][t][1], af[mt][t][2], af[mt][t][3], ad);
                }
            // 3 combos: h1g1, h1g2, h2g1 -> all into cr
            #pragma unroll
            for (int mt = 0; mt < 2; ++mt) {
                MMAH(cr[mt][0], af[mt][0], Bc[0].x, Bc[0].y);
                MMAH(cr[mt][1], af[mt][0], Bc[0].z, Bc[0].w);
                MMAH(cr[mt][2], af[mt][0], Bc[1].x, Bc[1].y);
                MMAH(cr[mt][3], af[mt][0], Bc[1].z, Bc[1].w);

                MMAH(cr[mt][0], af[mt][0], Bc[2].x, Bc[2].y);
                MMAH(cr[mt][1], af[mt][0], Bc[2].z, Bc[2].w);
                MMAH(cr[mt][2], af[mt][0], Bc[3].x, Bc[3].y);
                MMAH(cr[mt][3], af[mt][0], Bc[3].z, Bc[3].w);

                MMAH(cr[mt][0], af[mt][1], Bc[0].x, Bc[0].y);
                MMAH(cr[mt][1], af[mt][1], Bc[0].z, Bc[0].w);
                MMAH(cr[mt][2], af[mt][1], Bc[1].x, Bc[1].y);
                MMAH(cr[mt][3], af[mt][1], Bc[1].z, Bc[1].w);
            }
            #pragma unroll
            for (int t = 0; t < 4; ++t) Bc[t] = Bn[t];
        }
        if (c & 1) {
            // 2Sum fold: cr -> s_, residue stays in cr
            #pragma unroll
            for (int mt = 0; mt < 2; ++mt)
                #pragma unroll
                for (int nt = 0; nt < 4; ++nt)
                    #pragma unroll
                    for (int i = 0; i < 4; ++i) {
                        float a = s_[mt][nt][i], b = cr[mt][nt][i];
                        float t1 = a + b;
                        float z  = t1 - a;
                        float e  = (a - (t1 - z)) + (b - z);
                        s_[mt][nt][i] = t1;
                        cr[mt][nt][i] = e;
                    }
        }

        if (c < 63) {                              // split + store buf nxt
            uint32_t o1[8], o2[8];
            splitpairh(pa0.x, pa0.y, o1[0], o2[0]);
            splitpairh(pa0.z, pa0.w, o1[1], o2[1]);
            splitpairh(pa1.x, pa1.y, o1[2], o2[2]);
            splitpairh(pa1.z, pa1.w, o1[3], o2[3]);
            splitpairh(pa2.x, pa2.y, o1[4], o2[4]);
            splitpairh(pa2.z, pa2.w, o1[5], o2[5]);
            splitpairh(pa3.x, pa3.y, o1[6], o2[6]);
            splitpairh(pa3.z, pa3.w, o1[7], o2[7]);
            char* b0 = sm.tiles + (cur ^ 1) * BUF_BT + stOff;
            *(uint4*)(b0)                = make_uint4(o1[0], o1[1], o1[2], o1[3]);
            *(uint4*)(b0 + 16)           = make_uint4(o1[4], o1[5], o1[6], o1[7]);
            *(uint4*)(b0 + TERM_BT)      = make_uint4(o2[0], o2[1], o2[2], o2[3]);
            *(uint4*)(b0 + TERM_BT + 16) = make_uint4(o2[4], o2[5], o2[6], o2[7]);
        }
        __syncthreads();
    }

    // ---- stage logits into Cs ----
    #pragma unroll
    for (int mt = 0; mt < 2; ++mt)
        #pragma unroll
        for (int nt = 0; nt < 4; ++nt) {
            const int r  = wr * 32 + mt * 16 + (lane >> 2);
            const int c0 = wc * 32 + nt * 8 + (lane & 3) * 2;
            sm.Cs[r][c0]         = s_[mt][nt][0] + cr[mt][nt][0];
            sm.Cs[r][c0 + 1]     = s_[mt][nt][1] + cr[mt][nt][1];
            sm.Cs[r + 8][c0]     = s_[mt][nt][2] + cr[mt][nt][2];
            sm.Cs[r + 8][c0 + 1] = s_[mt][nt][3] + cr[mt][nt][3];
        }
    __syncthreads();

    // ---- top-8 per token via REDUX; each warp handles 16 tokens ----
    const float blo = bias[lane];
    const float bhi = bias[lane + 32];

    #pragma unroll 1
    for (int tt = 0; tt < 16; ++tt) {
        const int m   = wid * 16 + tt;
        const int tok = tok0 + m;
        const float v0 = sm.Cs[m][lane];
        const float v1 = sm.Cs[m][lane + 32];
        unsigned c0 = __float_as_uint(v0 + blo);
        unsigned c1 = __float_as_uint(v1 + bhi);
        unsigned u0 = c0 ^ (((int)c0 >> 31) | 0x80000000u);
        unsigned u1 = c1 ^ (((int)c1 >> 31) | 0x80000000u);

        int sel_i = 0;
        #pragma unroll
        for (int k = 0; k < 8; ++k) {
            unsigned cu; int ci;
            if (u1 > u0) { cu = u1; ci = lane + 32; }
            else         { cu = u0; ci = lane; }
            unsigned mx = __reduce_max_sync(0xffffffffu, cu);
            unsigned cand = (cu == mx) ? (unsigned)ci : 1000u;
            int wi = (int)__reduce_min_sync(0xffffffffu, cand);
            if (lane == k) sel_i = wi;
            if (wi < 32) { if (lane == wi)      u0 = 0u; }
            else         { if (lane == wi - 32) u1 = 0u; }
        }

        float p = 0.0f;
        if (lane < 8) {
            float raw = sm.Cs[m][sel_i];
            p = 1.0f / (1.0f + __expf(-raw));
        }
        float s = p;
        #pragma unroll
        for (int off = 4; off; off >>= 1) s += __shfl_xor_sync(0xffffffffu, s, off);
        s = fmaxf(s, 1e-12f);

        if (lane < 8) {
            out[(size_t)tok * 8 + lane]         = (float)sel_i;
            out[(size_t)w_off + tok * 8 + lane] = p / s;
        }
    }
}

extern "C" void kernel_launch(void* const* d_in, const int* in_sizes, int n_in,
                              void* d_out, int out_size) {
    const float* X    = (const float*)d_in[0];
    const float* W    = (const float*)d_in[1];
    const float* bias = (const float*)d_in[2];
    float* out = (float*)d_out;

    const int T = in_sizes[0] / 2048;   // 16384 tokens
    const int w_off = out_size >> 1;

    w_split_kernel<<<64, 256>>>(W);
    moe_gate_mma<<<T / 64, 128>>>(X, bias, out, w_off);
}

// round 14
// speedup vs baseline: 1.6332x; 1.1102x over previous
#include <cuda_runtime.h>
#include <cuda_fp16.h>
#include <cstdint>

// R14 = R13 resubmit (broker infra failed twice; no kernel signal).
// R12 numerics (fp16 2-term split, 3 combos -> cr, fold every 2 chunks)
// with BM 64->32: grid 512 (single balanced wave, 3-4 CTAs/SM), warp tile
// 32 tok x 16 exp (mt=2, nt=2), launch_bounds(128,4).
// Output: [T*8 idx as float | T*8 weights].

#define MMAH(d, a, b0, b1)                                                    \
    asm volatile("mma.sync.aligned.m16n8k16.row.col.f32.f16.f16.f32 "         \
                 "{%0,%1,%2,%3}, {%4,%5,%6,%7}, {%8,%9}, {%0,%1,%2,%3};"      \
                 : "+f"((d)[0]), "+f"((d)[1]), "+f"((d)[2]), "+f"((d)[3])     \
                 : "r"((a)[0]), "r"((a)[1]), "r"((a)[2]), "r"((a)[3]),        \
                   "r"(b0), "r"(b1))

#define LDSM4(r0, r1, r2, r3, addr)                                           \
    asm volatile("ldmatrix.sync.aligned.m8n8.x4.shared.b16 {%0,%1,%2,%3}, [%4];" \
                 : "=r"(r0), "=r"(r1), "=r"(r2), "=r"(r3) : "r"(addr))

#define CVTPKH(d, lo, hi)                                                     \
    asm("cvt.rn.f16x2.f32 %0, %1, %2;" : "=r"(d) : "f"(hi), "f"(lo))

// B fragments: [ks(128)][term(2)][npair(4)][lane(32)] x uint4 = 512 KB
__device__ __align__(16) uint4 g_Bf[128 * 2 * 4 * 32];

static __device__ __forceinline__ void splitpairh(float lo, float hi,
                                                  uint32_t& o1, uint32_t& o2) {
    CVTPKH(o1, lo, hi);
    __half2 h = *reinterpret_cast<__half2*>(&o1);
    float2 b = __half22float2(h);
    float l1 = lo - b.x;
    float h1 = hi - b.y;
    CVTPKH(o2, l1, h1);
}

__global__ void w_split_kernel(const float* __restrict__ W) {
    int idx  = blockIdx.x * 256 + threadIdx.x;   // 0..16383
    int lane = idx & 31;
    int j    = (idx >> 5) & 3;                   // npair: experts j*16..j*16+15
    int ks   = idx >> 7;                         // k16 step 0..127
    int e_lo = j * 16 + (lane >> 2);
    int k    = ks * 16 + (lane & 3) * 2;

    const float* p = W + (size_t)e_lo * 2048 + k;
    float2 f0 = *(const float2*)p;
    float2 f1 = *(const float2*)(p + 8);
    float2 f2 = *(const float2*)(p + 8 * 2048);
    float2 f3 = *(const float2*)(p + 8 * 2048 + 8);

    uint4 q1, q2;
    splitpairh(f0.x, f0.y, q1.x, q2.x);
    splitpairh(f1.x, f1.y, q1.y, q2.y);
    splitpairh(f2.x, f2.y, q1.z, q2.z);
    splitpairh(f3.x, f3.y, q1.w, q2.w);
    g_Bf[((ks * 2 + 0) * 4 + j) * 32 + lane] = q1;
    g_Bf[((ks * 2 + 1) * 4 + j) * 32 + lane] = q2;
}

// smem: A tiles [buf(2)][term(2)][32 rows x 80B] = 10240 B; Cs overlays it.
#define TERM_BT 2560
#define BUF_BT  5120

__global__ __launch_bounds__(128, 4) void moe_gate_mma(
    const float* __restrict__ X,
    const float* __restrict__ bias,
    float* __restrict__ out,
    int w_off)
{
    __shared__ union {
        char  tiles[2 * BUF_BT];
        float Cs[32][65];
    } sm;

    const int tid  = threadIdx.x;
    const int lane = tid & 31;
    const int wid  = tid >> 5;           // 0..3 = N quarter (16 experts)
    const int tok0 = blockIdx.x * 32;

    uint32_t sb;
    asm("{ .reg .u64 t; cvta.to.shared.u64 t, %1; cvt.u32.u64 %0, t; }"
        : "=r"(sb) : "l"(sm.tiles));

    // A gmem loader: row = tid>>2 (0..31), k-off = (tid&3)*8 floats
    const int arow = tid >> 2;
    const int akf  = (tid & 3) * 8;
    const float* aP = X + (size_t)(tok0 + arow) * 2048 + akf;
    const int stOff = arow * 80 + akf * 2;         // byte offset in a term tile

    // B fragment pointer: npair = wid (experts wid*16..wid*16+15)
    const uint4* bP = g_Bf + wid * 32 + lane;

    // A LDSM lane offsets
    const int a_r  = (lane & 7) + ((lane >> 3) & 1) * 8;
    const int a_kb = ((lane >> 4) & 1) * 16;

    float s_[2][2][4], cr[2][2][4];
    #pragma unroll
    for (int mt = 0; mt < 2; ++mt)
        #pragma unroll
        for (int nt = 0; nt < 2; ++nt)
            #pragma unroll
            for (int i = 0; i < 4; ++i) { s_[mt][nt][i] = 0.0f; cr[mt][nt][i] = 0.0f; }

    // ---- chunk 0: load + split + store buf 0 ----
    {
        float4 p0 = *(const float4*)(aP);
        float4 p1 = *(const float4*)(aP + 4);
        uint32_t o1[4], o2[4];
        splitpairh(p0.x, p0.y, o1[0], o2[0]);
        splitpairh(p0.z, p0.w, o1[1], o2[1]);
        splitpairh(p1.x, p1.y, o1[2], o2[2]);
        splitpairh(p1.z, p1.w, o1[3], o2[3]);
        char* b0 = sm.tiles + stOff;
        *(uint4*)(b0)           = make_uint4(o1[0], o1[1], o1[2], o1[3]);
        *(uint4*)(b0 + TERM_BT) = make_uint4(o2[0], o2[1], o2[2], o2[3]);
    }
    uint4 Bc[2];                                   // [term]
    Bc[0] = bP[0];
    Bc[1] = bP[128];
    __syncthreads();

    float4 pa0, pa1;
    #pragma unroll 1
    for (int c = 0; c < 64; ++c) {
        const int cur = c & 1;
        if (c < 63) {                              // prefetch A chunk c+1
            const int o = (c + 1) * 32;
            pa0 = *(const float4*)(aP + o);
            pa1 = *(const float4*)(aP + o + 4);
        }
        #pragma unroll
        for (int ks = 0; ks < 2; ++ks) {
            // prefetch next B fragment set
            const int kn = (2 * c + ks + 1 < 128) ? 2 * c + ks + 1 : 127;
            uint4 Bn[2];
            Bn[0] = bP[kn * 256];
            Bn[1] = bP[kn * 256 + 128];
            // A fragments: 2 m-tiles x 2 terms
            uint32_t af[2][2][4];
            #pragma unroll
            for (int mt = 0; mt < 2; ++mt)
                #pragma unroll
                for (int t = 0; t < 2; ++t) {
                    uint32_t ad = sb + cur * BUF_BT + t * TERM_BT
                                + (mt * 16 + a_r) * 80 + a_kb + ks * 32;
                    LDSM4(af[mt][t][0], af[mt][t][1], af[mt][t][2], af[mt][t][3], ad);
                }
            // 3 combos: h1g1, h1g2, h2g1 -> all into cr
            #pragma unroll
            for (int mt = 0; mt < 2; ++mt) {
                MMAH(cr[mt][0], af[mt][0], Bc[0].x, Bc[0].y);
                MMAH(cr[mt][1], af[mt][0], Bc[0].z, Bc[0].w);

                MMAH(cr[mt][0], af[mt][0], Bc[1].x, Bc[1].y);
                MMAH(cr[mt][1], af[mt][0], Bc[1].z, Bc[1].w);

                MMAH(cr[mt][0], af[mt][1], Bc[0].x, Bc[0].y);
                MMAH(cr[mt][1], af[mt][1], Bc[0].z, Bc[0].w);
            }
            Bc[0] = Bn[0];
            Bc[1] = Bn[1];
        }
        if (c & 1) {
            // 2Sum fold: cr -> s_, residue stays in cr
            #pragma unroll
            for (int mt = 0; mt < 2; ++mt)
                #pragma unroll
                for (int nt = 0; nt < 2; ++nt)
                    #pragma unroll
                    for (int i = 0; i < 4; ++i) {
                        float a = s_[mt][nt][i], b = cr[mt][nt][i];
                        float t1 = a + b;
                        float z  = t1 - a;
                        float e  = (a - (t1 - z)) + (b - z);
                        s_[mt][nt][i] = t1;
                        cr[mt][nt][i] = e;
                    }
        }

        if (c < 63) {                              // split + store buf nxt
            uint32_t o1[4], o2[4];
            splitpairh(pa0.x, pa0.y, o1[0], o2[0]);
            splitpairh(pa0.z, pa0.w, o1[1], o2[1]);
            splitpairh(pa1.x, pa1.y, o1[2], o2[2]);
            splitpairh(pa1.z, pa1.w, o1[3], o2[3]);
            char* b0 = sm.tiles + (cur ^ 1) * BUF_BT + stOff;
            *(uint4*)(b0)           = make_uint4(o1[0], o1[1], o1[2], o1[3]);
            *(uint4*)(b0 + TERM_BT) = make_uint4(o2[0], o2[1], o2[2], o2[3]);
        }
        __syncthreads();
    }

    // ---- stage logits into Cs ----
    #pragma unroll
    for (int mt = 0; mt < 2; ++mt)
        #pragma unroll
        for (int nt = 0; nt < 2; ++nt) {
            const int r  = mt * 16 + (lane >> 2);
            const int c0 = wid * 16 + nt * 8 + (lane & 3) * 2;
            sm.Cs[r][c0]         = s_[mt][nt][0] + cr[mt][nt][0];
            sm.Cs[r][c0 + 1]     = s_[mt][nt][1] + cr[mt][nt][1];
            sm.Cs[r + 8][c0]     = s_[mt][nt][2] + cr[mt][nt][2];
            sm.Cs[r + 8][c0 + 1] = s_[mt][nt][3] + cr[mt][nt][3];
        }
    __syncthreads();

    // ---- top-8 per token via REDUX; each warp handles 8 tokens ----
    const float blo = bias[lane];
    const float bhi = bias[lane + 32];

    #pragma unroll 1
    for (int tt = 0; tt < 8; ++tt) {
        const int m   = wid * 8 + tt;
        const int tok = tok0 + m;
        const float v0 = sm.Cs[m][lane];
        const float v1 = sm.Cs[m][lane + 32];
        unsigned c0 = __float_as_uint(v0 + blo);
        unsigned c1 = __float_as_uint(v1 + bhi);
        unsigned u0 = c0 ^ (((int)c0 >> 31) | 0x80000000u);
        unsigned u1 = c1 ^ (((int)c1 >> 31) | 0x80000000u);

        int sel_i = 0;
        #pragma unroll
        for (int k = 0; k < 8; ++k) {
            unsigned cu; int ci;
            if (u1 > u0) { cu = u1; ci = lane + 32; }
            else         { cu = u0; ci = lane; }
            unsigned mx = __reduce_max_sync(0xffffffffu, cu);
            unsigned cand = (cu == mx) ? (unsigned)ci : 1000u;
            int wi = (int)__reduce_min_sync(0xffffffffu, cand);
            if (lane == k) sel_i = wi;
            if (wi < 32) { if (lane == wi)      u0 = 0u; }
            else         { if (lane == wi - 32) u1 = 0u; }
        }

        float p = 0.0f;
        if (lane < 8) {
            float raw = sm.Cs[m][sel_i];
            p = 1.0f / (1.0f + __expf(-raw));
        }
        float s = p;
        #pragma unroll
        for (int off = 4; off; off >>= 1) s += __shfl_xor_sync(0xffffffffu, s, off);
        s = fmaxf(s, 1e-12f);

        if (lane < 8) {
            out[(size_t)tok * 8 + lane]         = (float)sel_i;
            out[(size_t)w_off + tok * 8 + lane] = p / s;
        }
    }
}

extern "C" void kernel_launch(void* const* d_in, const int* in_sizes, int n_in,
                              void* d_out, int out_size) {
    const float* X    = (const float*)d_in[0];
    const float* W    = (const float*)d_in[1];
    const float* bias = (const float*)d_in[2];
    float* out = (float*)d_out;

    const int T = in_sizes[0] / 2048;   // 16384 tokens
    const int w_off = out_size >> 1;

    w_split_kernel<<<64, 256>>>(W);
    moe_gate_mma<<<T / 32, 128>>>(X, bias, out, w_off);
}

// round 15
// speedup vs baseline: 1.8254x; 1.1176x over previous
#include <cuda_runtime.h>
#include <cuda_fp16.h>
#include <cstdint>

// R15: BM 16 (grid 1024, ~7 CTAs/SM), warp tile 16 tok x 16 exp (mt=1, nt=2),
// launch_bounds(128,6). Same proven numerics: fp16 2-term split, 3 combos
// -> cr, 2Sum fold cr->s_ every 2 chunks. A via smem split (shared per CTA,
// LDSM), B via pre-permuted fragment LDG. Output: [T*8 idx | T*8 w].

#define MMAH(d, a, b0, b1)                                                    \
    asm volatile("mma.sync.aligned.m16n8k16.row.col.f32.f16.f16.f32 "         \
                 "{%0,%1,%2,%3}, {%4,%5,%6,%7}, {%8,%9}, {%0,%1,%2,%3};"      \
                 : "+f"((d)[0]), "+f"((d)[1]), "+f"((d)[2]), "+f"((d)[3])     \
                 : "r"((a)[0]), "r"((a)[1]), "r"((a)[2]), "r"((a)[3]),        \
                   "r"(b0), "r"(b1))

#define LDSM4(r0, r1, r2, r3, addr)                                           \
    asm volatile("ldmatrix.sync.aligned.m8n8.x4.shared.b16 {%0,%1,%2,%3}, [%4];" \
                 : "=r"(r0), "=r"(r1), "=r"(r2), "=r"(r3) : "r"(addr))

#define CVTPKH(d, lo, hi)                                                     \
    asm("cvt.rn.f16x2.f32 %0, %1, %2;" : "=r"(d) : "f"(hi), "f"(lo))

// B fragments: [ks(128)][term(2)][npair(4)][lane(32)] x uint4 = 512 KB
__device__ __align__(16) uint4 g_Bf[128 * 2 * 4 * 32];

static __device__ __forceinline__ void splitpairh(float lo, float hi,
                                                  uint32_t& o1, uint32_t& o2) {
    CVTPKH(o1, lo, hi);
    __half2 h = *reinterpret_cast<__half2*>(&o1);
    float2 b = __half22float2(h);
    float l1 = lo - b.x;
    float h1 = hi - b.y;
    CVTPKH(o2, l1, h1);
}

__global__ void w_split_kernel(const float* __restrict__ W) {
    int idx  = blockIdx.x * 256 + threadIdx.x;   // 0..16383
    int lane = idx & 31;
    int j    = (idx >> 5) & 3;                   // npair: experts j*16..j*16+15
    int ks   = idx >> 7;                         // k16 step 0..127
    int e_lo = j * 16 + (lane >> 2);
    int k    = ks * 16 + (lane & 3) * 2;

    const float* p = W + (size_t)e_lo * 2048 + k;
    float2 f0 = *(const float2*)p;
    float2 f1 = *(const float2*)(p + 8);
    float2 f2 = *(const float2*)(p + 8 * 2048);
    float2 f3 = *(const float2*)(p + 8 * 2048 + 8);

    uint4 q1, q2;
    splitpairh(f0.x, f0.y, q1.x, q2.x);
    splitpairh(f1.x, f1.y, q1.y, q2.y);
    splitpairh(f2.x, f2.y, q1.z, q2.z);
    splitpairh(f3.x, f3.y, q1.w, q2.w);
    g_Bf[((ks * 2 + 0) * 4 + j) * 32 + lane] = q1;
    g_Bf[((ks * 2 + 1) * 4 + j) * 32 + lane] = q2;
}

// smem: A tiles [buf(2)][term(2)][16 rows x 80B] = 5120 B; Cs overlays it.
#define TERM_BT 1280
#define BUF_BT  2560

__global__ __launch_bounds__(128, 6) void moe_gate_mma(
    const float* __restrict__ X,
    const float* __restrict__ bias,
    float* __restrict__ out,
    int w_off)
{
    __shared__ union {
        char  tiles[2 * BUF_BT];
        float Cs[16][65];
    } sm;

    const int tid  = threadIdx.x;
    const int lane = tid & 31;
    const int wid  = tid >> 5;           // 0..3 = N quarter (16 experts)
    const int tok0 = blockIdx.x * 16;

    uint32_t sb;
    asm("{ .reg .u64 t; cvta.to.shared.u64 t, %1; cvt.u32.u64 %0, t; }"
        : "=r"(sb) : "l"(sm.tiles));

    // A gmem loader: row = tid>>3 (0..15), k-off = (tid&7)*4 floats
    const int arow = tid >> 3;
    const int akf  = (tid & 7) * 4;
    const float* aP = X + (size_t)(tok0 + arow) * 2048 + akf;
    const int stOff = arow * 80 + akf * 2;         // byte offset in a term tile

    // B fragment pointer: npair = wid (experts wid*16..wid*16+15)
    const uint4* bP = g_Bf + wid * 32 + lane;

    // A LDSM lane offsets (x4 over a 16-row tile)
    const int a_r  = (lane & 7) + ((lane >> 3) & 1) * 8;
    const int a_kb = ((lane >> 4) & 1) * 16;

    float s_[2][4], cr[2][4];
    #pragma unroll
    for (int nt = 0; nt < 2; ++nt)
        #pragma unroll
        for (int i = 0; i < 4; ++i) { s_[nt][i] = 0.0f; cr[nt][i] = 0.0f; }

    // ---- chunk 0: load + split + store buf 0 ----
    {
        float4 p0 = *(const float4*)(aP);
        uint32_t o1[2], o2[2];
        splitpairh(p0.x, p0.y, o1[0], o2[0]);
        splitpairh(p0.z, p0.w, o1[1], o2[1]);
        char* b0 = sm.tiles + stOff;
        *(uint2*)(b0)           = make_uint2(o1[0], o1[1]);
        *(uint2*)(b0 + TERM_BT) = make_uint2(o2[0], o2[1]);
    }
    uint4 Bc[2];                                   // [term]
    Bc[0] = bP[0];
    Bc[1] = bP[128];
    __syncthreads();

    float4 pa0;
    #pragma unroll 1
    for (int c = 0; c < 64; ++c) {
        const int cur = c & 1;
        if (c < 63)                                // prefetch A chunk c+1
            pa0 = *(const float4*)(aP + (c + 1) * 32);

        #pragma unroll
        for (int ks = 0; ks < 2; ++ks) {
            // prefetch next B fragment set
            const int kn = (2 * c + ks + 1 < 128) ? 2 * c + ks + 1 : 127;
            uint4 Bn[2];
            Bn[0] = bP[kn * 256];
            Bn[1] = bP[kn * 256 + 128];
            // A fragments: 2 terms (single 16-row m-tile)
            uint32_t af[2][4];
            #pragma unroll
            for (int t = 0; t < 2; ++t) {
                uint32_t ad = sb + cur * BUF_BT + t * TERM_BT
                            + a_r * 80 + a_kb + ks * 32;
                LDSM4(af[t][0], af[t][1], af[t][2], af[t][3], ad);
            }
            // 3 combos: h1g1, h1g2, h2g1 -> all into cr
            MMAH(cr[0], af[0], Bc[0].x, Bc[0].y);
            MMAH(cr[1], af[0], Bc[0].z, Bc[0].w);

            MMAH(cr[0], af[0], Bc[1].x, Bc[1].y);
            MMAH(cr[1], af[0], Bc[1].z, Bc[1].w);

            MMAH(cr[0], af[1], Bc[0].x, Bc[0].y);
            MMAH(cr[1], af[1], Bc[0].z, Bc[0].w);

            Bc[0] = Bn[0];
            Bc[1] = Bn[1];
        }
        if (c & 1) {
            // 2Sum fold: cr -> s_, residue stays in cr
            #pragma unroll
            for (int nt = 0; nt < 2; ++nt)
                #pragma unroll
                for (int i = 0; i < 4; ++i) {
                    float a = s_[nt][i], b = cr[nt][i];
                    float t1 = a + b;
                    float z  = t1 - a;
                    float e  = (a - (t1 - z)) + (b - z);
                    s_[nt][i] = t1;
                    cr[nt][i] = e;
                }
        }

        if (c < 63) {                              // split + store buf nxt
            uint32_t o1[2], o2[2];
            splitpairh(pa0.x, pa0.y, o1[0], o2[0]);
            splitpairh(pa0.z, pa0.w, o1[1], o2[1]);
            char* b0 = sm.tiles + (cur ^ 1) * BUF_BT + stOff;
            *(uint2*)(b0)           = make_uint2(o1[0], o1[1]);
            *(uint2*)(b0 + TERM_BT) = make_uint2(o2[0], o2[1]);
        }
        __syncthreads();
    }

    // ---- stage logits into Cs ----
    #pragma unroll
    for (int nt = 0; nt < 2; ++nt) {
        const int r  = lane >> 2;
        const int c0 = wid * 16 + nt * 8 + (lane & 3) * 2;
        sm.Cs[r][c0]         = s_[nt][0] + cr[nt][0];
        sm.Cs[r][c0 + 1]     = s_[nt][1] + cr[nt][1];
        sm.Cs[r + 8][c0]     = s_[nt][2] + cr[nt][2];
        sm.Cs[r + 8][c0 + 1] = s_[nt][3] + cr[nt][3];
    }
    __syncthreads();

    // ---- top-8 per token via REDUX; each warp handles 4 tokens ----
    const float blo = bias[lane];
    const float bhi = bias[lane + 32];

    #pragma unroll 1
    for (int tt = 0; tt < 4; ++tt) {
        const int m   = wid * 4 + tt;
        const int tok = tok0 + m;
        const float v0 = sm.Cs[m][lane];
        const float v1 = sm.Cs[m][lane + 32];
        unsigned c0 = __float_as_uint(v0 + blo);
        unsigned c1 = __float_as_uint(v1 + bhi);
        unsigned u0 = c0 ^ (((int)c0 >> 31) | 0x80000000u);
        unsigned u1 = c1 ^ (((int)c1 >> 31) | 0x80000000u);

        int sel_i = 0;
        #pragma unroll
        for (int k = 0; k < 8; ++k) {
            unsigned cu; int ci;
            if (u1 > u0) { cu = u1; ci = lane + 32; }
            else         { cu = u0; ci = lane; }
            unsigned mx = __reduce_max_sync(0xffffffffu, cu);
            unsigned cand = (cu == mx) ? (unsigned)ci : 1000u;
            int wi = (int)__reduce_min_sync(0xffffffffu, cand);
            if (lane == k) sel_i = wi;
            if (wi < 32) { if (lane == wi)      u0 = 0u; }
            else         { if (lane == wi - 32) u1 = 0u; }
        }

        float p = 0.0f;
        if (lane < 8) {
            float raw = sm.Cs[m][sel_i];
            p = 1.0f / (1.0f + __expf(-raw));
        }
        float s = p;
        #pragma unroll
        for (int off = 4; off; off >>= 1) s += __shfl_xor_sync(0xffffffffu, s, off);
        s = fmaxf(s, 1e-12f);

        if (lane < 8) {
            out[(size_t)tok * 8 + lane]         = (float)sel_i;
            out[(size_t)w_off + tok * 8 + lane] = p / s;
        }
    }
}

extern "C" void kernel_launch(void* const* d_in, const int* in_sizes, int n_in,
                              void* d_out, int out_size) {
    const float* X    = (const float*)d_in[0];
    const float* W    = (const float*)d_in[1];
    const float* bias = (const float*)d_in[2];
    float* out = (float*)d_out;

    const int T = in_sizes[0] / 2048;   // 16384 tokens
    const int w_off = out_size >> 1;

    w_split_kernel<<<64, 256>>>(W);
    moe_gate_mma<<<T / 16, 128>>>(X, bias, out, w_off);
}